// round 11
// baseline (speedup 1.0000x reference)
#include <cuda_runtime.h>
#include <cuda_fp16.h>
#include <cstdint>

// CostVolume: cost[b,i,h,x] = (1/128) sum_c L[b,c,h,x]*R[b,c,h,x-i], 0 for x<i.
// b=8 c=128 h=96 w=320, 48 disp, fp32.
// v11 = v8 structure (fp16 mma.sync.m16n8k16, fp32 accum, K in 4 slices of 32,
// register prefetch, 1 barrier/slice) widened to 512 threads / 16 warps:
// warp = (m-tile 16) x (2 n-tiles); convert warp-specialized (A: warps 0-7,
// B: warps 8-15). Traffic is already compulsory-minimal; this buys occupancy.

#define BB 8
#define CH 128
#define HH 96
#define WW 320
#define MAXD 48
#define PLANE (HH*WW)

#define ROWB 256         // fp16 tile row bytes: 128 k * 2B
#define AF 0             // A fp16: 64*256  = 16384
#define BF 16384         // B fp16: 112*256 = 28672
#define SMEM_TOTAL 45056
#define NTHR 512

// col-perm swizzle: bijective on consecutive-8 rows (ldmatrix) and stride-4 rows (STS)
__device__ __forceinline__ uint32_t gfun(uint32_t m){
    return ((((m>>2)&1)<<2) | ((((m>>1)^(m>>4))&1)<<1) | (((m^(m>>3))&1)));
}
__device__ __forceinline__ uint32_t smem_u32(const void* p){
    uint32_t a;
    asm("{ .reg .u64 t; cvta.to.shared.u64 t, %1; cvt.u32.u64 %0, t; }" : "=r"(a) : "l"(p));
    return a;
}
__device__ __forceinline__ uint32_t cvt_f16x2(float v0, float v1){
    uint32_t r;
    asm("cvt.rn.f16x2.f32 %0, %1, %2;" : "=r"(r) : "f"(v1), "f"(v0));
    return r;
}
__device__ __forceinline__ void ldsm_x4(uint32_t* r, uint32_t addr){
    asm volatile("ldmatrix.sync.aligned.m8n8.x4.shared.b16 {%0,%1,%2,%3}, [%4];"
                 : "=r"(r[0]), "=r"(r[1]), "=r"(r[2]), "=r"(r[3]) : "r"(addr));
}
__device__ __forceinline__ void mma16816(float* c, const uint32_t* a, const uint32_t* b){
    asm volatile("mma.sync.aligned.m16n8k16.row.col.f32.f16.f16.f32 "
                 "{%0,%1,%2,%3}, {%4,%5,%6,%7}, {%8,%9}, {%0,%1,%2,%3};"
                 : "+f"(c[0]), "+f"(c[1]), "+f"(c[2]), "+f"(c[3])
                 : "r"(a[0]), "r"(a[1]), "r"(a[2]), "r"(a[3]), "r"(b[0]), "r"(b[1]));
}
__device__ __forceinline__ float4 zero4(){ return make_float4(0.f,0.f,0.f,0.f); }

__global__ __launch_bounds__(NTHR, 3)
void costvol_v11_kernel(const float* __restrict__ L,
                        const float* __restrict__ R,
                        float* __restrict__ out)
{
    extern __shared__ char smem[];
    const uint32_t sb = smem_u32(smem);

    const int tid  = threadIdx.x;        // 0..511
    const int warp = tid >> 5;           // 0..15
    const int lane = tid & 31;

    const int xt = blockIdx.x % 5;
    const int bh = blockIdx.x / 5;
    const int h  = bh % HH;
    const int b  = bh / HH;
    const int X0 = 64 * xt;

    const float* Lbh = L + ((size_t)b * CH * HH + h) * WW;
    const float* Rbh = R + ((size_t)b * CH * HH + h) * WW;

    // ---- convert roles: warps 0-7 do A, warps 8-15 do B ----
    const bool isA = (tid < 256);
    // A task (tid 0..255): kp = tid>>4 (0..15), m4 = tid&15
    const int kplA = tid >> 4;
    const int m4a  = tid & 15;
    const float* pLa = Lbh + X0 + 4 * m4a;
    uint32_t gA[4];
    #pragma unroll
    for (int e = 0; e < 4; e++) gA[e] = gfun((uint32_t)(4*m4a + e));

    // B tasks (t2 = tid-256, 0..255): task0 = t2, task1 = t2+256 (t2<192)
    const int t2 = tid - 256;
    const int kplB0 = (t2 < 0 ? 0 : t2) / 28;
    const int n4b0  = (t2 < 0 ? 0 : t2) - 28 * kplB0;
    const bool act1 = (!isA) && (t2 < 192);
    const int tB1 = t2 + 256;
    const int kplB1 = act1 ? tB1 / 28 : 0;
    const int n4b1  = act1 ? (tB1 - 28 * kplB1) : 0;
    const int xrB0 = X0 - 48 + 4 * n4b0;
    const int xrB1 = X0 - 48 + 4 * n4b1;
    uint32_t gB0[4], gB1[4];
    #pragma unroll
    for (int e = 0; e < 4; e++){
        gB0[e] = gfun((uint32_t)(4*n4b0 + e));
        gB1[e] = gfun((uint32_t)(4*n4b1 + e));
    }

    // ---- mma lane constants: warp = (mt = warp>>2) x (nq = warp&3) ----
    const int mt = warp >> 2;            // 0..3
    const int nq = warp & 3;             // 0..3
    const int m0 = 16 * mt;
    const int pbase = 2*mt + 2*nq;       // n-tiles pbase, pbase+1
    const int lg = lane >> 3, l8 = lane & 7;
    const int arow = m0 + l8 + ((lg & 1) ? 8 : 0);
    const int asel = lg >> 1;
    const uint32_t gArow = gfun((uint32_t)arow);
    const int colselB = (lane >> 3) & 1;
    const int brow = 8 * (pbase + ((lane >> 4) & 1)) + (lane & 7);
    const uint32_t gBr = gfun((uint32_t)brow);

    float C[2][4];
    #pragma unroll
    for (int t = 0; t < 2; t++)
        #pragma unroll
        for (int f = 0; f < 4; f++) C[t][f] = 0.f;

    float4 a0, a1, b00, b01, b10, b11;

    auto prefetch = [&](int kc){
        if (isA){
            int c0a = 2 * (kc * 16 + kplA);
            a0 = *(const float4*)(pLa + (size_t)c0a * PLANE);
            a1 = *(const float4*)(pLa + (size_t)(c0a + 1) * PLANE);
        } else {
            int c0b = 2 * (kc * 16 + kplB0);
            if (xrB0 >= 0){
                b00 = *(const float4*)(Rbh + (size_t)c0b * PLANE + xrB0);
                b01 = *(const float4*)(Rbh + (size_t)(c0b + 1) * PLANE + xrB0);
            } else { b00 = zero4(); b01 = zero4(); }
            if (act1 && xrB1 >= 0){
                int c1b = 2 * (kc * 16 + kplB1);
                b10 = *(const float4*)(Rbh + (size_t)c1b * PLANE + xrB1);
                b11 = *(const float4*)(Rbh + (size_t)(c1b + 1) * PLANE + xrB1);
            } else { b10 = zero4(); b11 = zero4(); }
        }
    };

    auto convert_sts = [&](int kc){
        if (isA){
            uint32_t kpg = (uint32_t)(kc * 16 + kplA);
            uint32_t c16 = kpg >> 2, w4 = (kpg & 3) << 2;
            const float va[4] = {a0.x, a0.y, a0.z, a0.w};
            const float vb[4] = {a1.x, a1.y, a1.z, a1.w};
            #pragma unroll
            for (int e = 0; e < 4; e++){
                uint32_t m = (uint32_t)(4*m4a + e);
                uint32_t off = m * ROWB + ((c16 ^ gA[e]) << 4) + w4;
                *(uint32_t*)(smem + AF + off) = cvt_f16x2(va[e], vb[e]);
            }
        } else {
            {
                uint32_t kpg = (uint32_t)(kc * 16 + kplB0);
                uint32_t c16 = kpg >> 2, w4 = (kpg & 3) << 2;
                const float va[4] = {b00.x, b00.y, b00.z, b00.w};
                const float vb[4] = {b01.x, b01.y, b01.z, b01.w};
                #pragma unroll
                for (int e = 0; e < 4; e++){
                    uint32_t n = (uint32_t)(4*n4b0 + e);
                    uint32_t off = n * ROWB + ((c16 ^ gB0[e]) << 4) + w4;
                    *(uint32_t*)(smem + BF + off) = cvt_f16x2(va[e], vb[e]);
                }
            }
            if (act1){
                uint32_t kpg = (uint32_t)(kc * 16 + kplB1);
                uint32_t c16 = kpg >> 2, w4 = (kpg & 3) << 2;
                const float va[4] = {b10.x, b10.y, b10.z, b10.w};
                const float vb[4] = {b11.x, b11.y, b11.z, b11.w};
                #pragma unroll
                for (int e = 0; e < 4; e++){
                    uint32_t n = (uint32_t)(4*n4b1 + e);
                    uint32_t off = n * ROWB + ((c16 ^ gB1[e]) << 4) + w4;
                    *(uint32_t*)(smem + BF + off) = cvt_f16x2(va[e], vb[e]);
                }
            }
        }
    };

    // ---- pipelined main loop: convert(kc) | prefetch(kc+1) | bar | mma(kc) ----
    prefetch(0);
    #pragma unroll 1
    for (int kc = 0; kc < 4; kc++){
        convert_sts(kc);
        if (kc < 3) prefetch(kc + 1);
        __syncthreads();                 // slice kc visible to all warps

        #pragma unroll
        for (int ktl = 0; ktl < 2; ktl++){
            uint32_t colA = (uint32_t)(kc * 4 + 2 * ktl + asel);
            uint32_t aoff = (uint32_t)arow * ROWB + ((colA ^ gArow) << 4);
            uint32_t af[4];
            ldsm_x4(af, sb + AF + aoff);
            uint32_t colB = (uint32_t)(kc * 4 + 2 * ktl + colselB);
            uint32_t boff = (uint32_t)brow * ROWB + ((colB ^ gBr) << 4);
            uint32_t bf[4];
            ldsm_x4(bf, sb + BF + boff);
            mma16816(C[0], af, bf);       // n-tile pbase
            mma16816(C[1], af, bf + 2);   // n-tile pbase+1
        }
        // no 2nd barrier: next convert writes a disjoint k-slice
    }
    __syncthreads();                     // all mma done before Obuf overlays A

    // ---- band extract into Obuf[i][m] (stride 68), scale 1/128 ----
    float* Ob = (float*)smem;            // 48*68*4 = 13056 B
    const int r  = lane >> 2;
    const int cb = 2 * (lane & 3);
    const float scale = 1.0f / 128.0f;
    #pragma unroll
    for (int j = 0; j < 2; j++){
        int p = pbase + j;
        #pragma unroll
        for (int f = 0; f < 4; f++){
            int row  = r + ((f >= 2) ? 8 : 0);
            int col  = cb + (f & 1);
            int mloc = m0 + row;
            int n    = 8*p + col;
            int i    = mloc + 48 - n;
            if (i >= 0 && i < MAXD)
                Ob[i * 68 + mloc] = C[j][f] * scale;
        }
    }
    __syncthreads();

    // ---- coalesced store: 48 rows x 64 floats ----
    float* ob = out + (((size_t)b * MAXD) * HH + h) * WW + X0;
    #pragma unroll
    for (int q = tid; q < MAXD * 16; q += NTHR){
        int i = q >> 4, c4 = q & 15;
        float4 v = *(const float4*)(Ob + i * 68 + 4 * c4);
        *(float4*)(ob + (size_t)i * PLANE + 4 * c4) = v;
    }
}

extern "C" void kernel_launch(void* const* d_in, const int* in_sizes, int n_in,
                              void* d_out, int out_size)
{
    const float* L = (const float*)d_in[0];
    const float* R = (const float*)d_in[1];
    float* out = (float*)d_out;

    cudaFuncSetAttribute(costvol_v11_kernel,
                         cudaFuncAttributeMaxDynamicSharedMemorySize, SMEM_TOTAL);
    dim3 grid(BB * HH * 5);   // 3840 CTAs: (b, h, x-tile of 64)
    costvol_v11_kernel<<<grid, NTHR, SMEM_TOTAL>>>(L, R, out);
}

// round 12
// speedup vs baseline: 1.7079x; 1.7079x over previous
#include <cuda_runtime.h>
#include <cuda_fp16.h>
#include <cstdint>

// CostVolume: cost[b,i,h,x] = (1/128) sum_c L[b,c,h,x]*R[b,c,h,x-i], 0 for x<i.
// b=8 c=128 h=96 w=320, 48 disp, fp32.
// v12 = v8 (best: 62us) with register diet for 4 CTAs/SM:
//   - swizzle constants recomputed per use (gfun is ~4 LOP3) instead of cached
//   - __launch_bounds__(256, 4) -> 64-reg target, 32 warps/SM
// Structure (K in 4 slices of 32, register prefetch, 1 barrier/slice,
// fp16 mma.sync.m16n8k16 with fp32 accum) is byte-identical to v8.

#define BB 8
#define CH 128
#define HH 96
#define WW 320
#define MAXD 48
#define PLANE (HH*WW)

#define ROWB 256         // fp16 tile row bytes: 128 k * 2B
#define AF 0             // A fp16: 64*256  = 16384
#define BF 16384         // B fp16: 112*256 = 28672
#define SMEM_TOTAL 45056

// col-perm swizzle: bijective on consecutive-8 rows (ldmatrix) and stride-4 rows (STS)
__device__ __forceinline__ uint32_t gfun(uint32_t m){
    return ((((m>>2)&1)<<2) | ((((m>>1)^(m>>4))&1)<<1) | (((m^(m>>3))&1)));
}
__device__ __forceinline__ uint32_t smem_u32(const void* p){
    uint32_t a;
    asm("{ .reg .u64 t; cvta.to.shared.u64 t, %1; cvt.u32.u64 %0, t; }" : "=r"(a) : "l"(p));
    return a;
}
__device__ __forceinline__ uint32_t cvt_f16x2(float v0, float v1){
    uint32_t r;
    asm("cvt.rn.f16x2.f32 %0, %1, %2;" : "=r"(r) : "f"(v1), "f"(v0));
    return r;
}
__device__ __forceinline__ void ldsm_x4(uint32_t* r, uint32_t addr){
    asm volatile("ldmatrix.sync.aligned.m8n8.x4.shared.b16 {%0,%1,%2,%3}, [%4];"
                 : "=r"(r[0]), "=r"(r[1]), "=r"(r[2]), "=r"(r[3]) : "r"(addr));
}
__device__ __forceinline__ void mma16816(float* c, const uint32_t* a, const uint32_t* b){
    asm volatile("mma.sync.aligned.m16n8k16.row.col.f32.f16.f16.f32 "
                 "{%0,%1,%2,%3}, {%4,%5,%6,%7}, {%8,%9}, {%0,%1,%2,%3};"
                 : "+f"(c[0]), "+f"(c[1]), "+f"(c[2]), "+f"(c[3])
                 : "r"(a[0]), "r"(a[1]), "r"(a[2]), "r"(a[3]), "r"(b[0]), "r"(b[1]));
}
__device__ __forceinline__ float4 zero4(){ return make_float4(0.f,0.f,0.f,0.f); }

__global__ __launch_bounds__(256, 4)
void costvol_v12_kernel(const float* __restrict__ L,
                        const float* __restrict__ R,
                        float* __restrict__ out)
{
    extern __shared__ char smem[];
    const uint32_t sb = smem_u32(smem);

    const int tid  = threadIdx.x;
    const int warp = tid >> 5;
    const int lane = tid & 31;

    const int xt = blockIdx.x % 5;
    const int bh = blockIdx.x / 5;
    const int h  = bh % HH;
    const int b  = bh / HH;
    const int X0 = 64 * xt;

    const float* Lbh = L + ((size_t)b * CH * HH + h) * WW;
    const float* Rbh = R + ((size_t)b * CH * HH + h) * WW;

    // ---- convert task indices (swizzle consts recomputed per use) ----
    const int kplA = tid >> 4;            // 0..15
    const int m4a  = tid & 15;
    const float* pLa = Lbh + X0 + 4 * m4a;

    const int kplB0 = tid / 28, n4b0 = tid - 28 * kplB0;
    const int tB1 = tid + 256;
    const bool act1 = (tB1 < 448);
    const int kplB1 = act1 ? tB1 / 28 : 0;
    const int n4b1  = act1 ? (tB1 - 28 * kplB1) : 0;
    const int xrB0 = X0 - 48 + 4 * n4b0;
    const int xrB1 = X0 - 48 + 4 * n4b1;

    // ---- mma lane constants ----
    const int mt = warp >> 1, nh = warp & 1;
    const int m0 = 16 * mt;
    const int lg = lane >> 3, l8 = lane & 7;
    const int arow = m0 + l8 + ((lg & 1) ? 8 : 0);
    const int asel = lg >> 1;
    const int colselB = (lane >> 3) & 1;

    float C[4][4];
    #pragma unroll
    for (int t = 0; t < 4; t++)
        #pragma unroll
        for (int f = 0; f < 4; f++) C[t][f] = 0.f;

    float4 a0, a1, b00, b01, b10, b11;

    auto prefetch = [&](int kc){
        int c0a = 2 * (kc * 16 + kplA);
        a0 = *(const float4*)(pLa + (size_t)c0a * PLANE);
        a1 = *(const float4*)(pLa + (size_t)(c0a + 1) * PLANE);
        int c0b = 2 * (kc * 16 + kplB0);
        if (xrB0 >= 0){
            b00 = *(const float4*)(Rbh + (size_t)c0b * PLANE + xrB0);
            b01 = *(const float4*)(Rbh + (size_t)(c0b + 1) * PLANE + xrB0);
        } else { b00 = zero4(); b01 = zero4(); }
        int c1b = 2 * (kc * 16 + kplB1);
        if (act1 && xrB1 >= 0){
            b10 = *(const float4*)(Rbh + (size_t)c1b * PLANE + xrB1);
            b11 = *(const float4*)(Rbh + (size_t)(c1b + 1) * PLANE + xrB1);
        } else { b10 = zero4(); b11 = zero4(); }
    };

    auto convert_sts = [&](int kc){
        {   // A slice
            uint32_t kpg = (uint32_t)(kc * 16 + kplA);
            uint32_t c16 = kpg >> 2, w4 = (kpg & 3) << 2;
            const float va[4] = {a0.x, a0.y, a0.z, a0.w};
            const float vb[4] = {a1.x, a1.y, a1.z, a1.w};
            #pragma unroll
            for (int e = 0; e < 4; e++){
                uint32_t m = (uint32_t)(4*m4a + e);
                uint32_t off = m * ROWB + ((c16 ^ gfun(m)) << 4) + w4;
                *(uint32_t*)(smem + AF + off) = cvt_f16x2(va[e], vb[e]);
            }
        }
        {   // B slice task 0
            uint32_t kpg = (uint32_t)(kc * 16 + kplB0);
            uint32_t c16 = kpg >> 2, w4 = (kpg & 3) << 2;
            const float va[4] = {b00.x, b00.y, b00.z, b00.w};
            const float vb[4] = {b01.x, b01.y, b01.z, b01.w};
            #pragma unroll
            for (int e = 0; e < 4; e++){
                uint32_t n = (uint32_t)(4*n4b0 + e);
                uint32_t off = n * ROWB + ((c16 ^ gfun(n)) << 4) + w4;
                *(uint32_t*)(smem + BF + off) = cvt_f16x2(va[e], vb[e]);
            }
        }
        if (act1){  // B slice task 1
            uint32_t kpg = (uint32_t)(kc * 16 + kplB1);
            uint32_t c16 = kpg >> 2, w4 = (kpg & 3) << 2;
            const float va[4] = {b10.x, b10.y, b10.z, b10.w};
            const float vb[4] = {b11.x, b11.y, b11.z, b11.w};
            #pragma unroll
            for (int e = 0; e < 4; e++){
                uint32_t n = (uint32_t)(4*n4b1 + e);
                uint32_t off = n * ROWB + ((c16 ^ gfun(n)) << 4) + w4;
                *(uint32_t*)(smem + BF + off) = cvt_f16x2(va[e], vb[e]);
            }
        }
    };

    // ---- pipelined main loop: convert(kc) | prefetch(kc+1) | bar | mma(kc) ----
    prefetch(0);
    #pragma unroll 1
    for (int kc = 0; kc < 4; kc++){
        convert_sts(kc);
        if (kc < 3) prefetch(kc + 1);
        __syncthreads();                 // slice kc visible to all warps

        #pragma unroll
        for (int ktl = 0; ktl < 2; ktl++){
            uint32_t colA = (uint32_t)(kc * 4 + 2 * ktl + asel);
            uint32_t aoff = (uint32_t)arow * ROWB + ((colA ^ gfun((uint32_t)arow)) << 4);
            uint32_t af[4];
            ldsm_x4(af, sb + AF + aoff);
            #pragma unroll
            for (int j = 0; j < 2; j++){
                int p = 2*mt + 4*nh + 2*j + ((lane >> 4) & 1);
                uint32_t brow = (uint32_t)(8*p + (lane & 7));
                uint32_t colB = (uint32_t)(kc * 4 + 2 * ktl + colselB);
                uint32_t boff = brow * ROWB + ((colB ^ gfun(brow)) << 4);
                uint32_t bf[4];
                ldsm_x4(bf, sb + BF + boff);
                mma16816(C[2*j],     af, bf);       // tn = 2j
                mma16816(C[2*j + 1], af, bf + 2);   // tn = 2j+1
            }
        }
        // no 2nd barrier: next convert writes a disjoint k-slice
    }
    __syncthreads();                     // all mma done before Obuf overlays A

    // ---- band extract into Obuf[i][m] (stride 68), scale 1/128 ----
    float* Ob = (float*)smem;            // 48*68*4 = 13056 B
    const int r  = lane >> 2;
    const int cb = 2 * (lane & 3);
    const float scale = 1.0f / 128.0f;
    #pragma unroll
    for (int tn = 0; tn < 4; tn++){
        int p = 2*mt + 4*nh + tn;
        #pragma unroll
        for (int f = 0; f < 4; f++){
            int row  = r + ((f >= 2) ? 8 : 0);
            int col  = cb + (f & 1);
            int mloc = m0 + row;
            int n    = 8*p + col;
            int i    = mloc + 48 - n;
            if (i >= 0 && i < MAXD)
                Ob[i * 68 + mloc] = C[tn][f] * scale;
        }
    }
    __syncthreads();

    // ---- coalesced store: 48 rows x 64 floats ----
    float* ob = out + (((size_t)b * MAXD) * HH + h) * WW + X0;
    #pragma unroll
    for (int q = tid; q < MAXD * 16; q += 256){
        int i = q >> 4, c4 = q & 15;
        float4 v = *(const float4*)(Ob + i * 68 + 4 * c4);
        *(float4*)(ob + (size_t)i * PLANE + 4 * c4) = v;
    }
}

extern "C" void kernel_launch(void* const* d_in, const int* in_sizes, int n_in,
                              void* d_out, int out_size)
{
    const float* L = (const float*)d_in[0];
    const float* R = (const float*)d_in[1];
    float* out = (float*)d_out;

    cudaFuncSetAttribute(costvol_v12_kernel,
                         cudaFuncAttributeMaxDynamicSharedMemorySize, SMEM_TOTAL);
    dim3 grid(BB * HH * 5);   // 3840 CTAs: (b, h, x-tile of 64)
    costvol_v12_kernel<<<grid, 256, SMEM_TOTAL>>>(L, R, out);
}